// round 14
// baseline (speedup 1.0000x reference)
#include <cuda_runtime.h>
#include <cuda_bf16.h>
#include <math.h>
#include <stdint.h>

#define T_STEPS 1024
#define BATCH   32
#define INP     512
#define HID     512
#define G4      2048   // 4*HID
#define MTOT    (T_STEPS * BATCH)   // 32768

// ---------------- scratch ----------------
__device__ signed char g_xq[(size_t)MTOT * 1024];    // x 2-limb int8 [m][c*128+limb*64+ko]
__device__ signed char g_hq[2][32 * 1024];           // h 2-limb int8 ping-pong
__device__ unsigned int g_bar;                       // grid barrier counter
__device__ unsigned int g_umax_bits;                 // max|U|
__device__ unsigned int g_xmax_bits;                 // max|x|
__device__ unsigned int g_wmax_bits;                 // max|W|

// ================= helpers =================
__device__ __forceinline__ uint32_t smem_to_u32(const void* p) {
    uint32_t a;
    asm("{ .reg .u64 t; cvta.to.shared.u64 t, %1; cvt.u32.u64 %0, t; }"
        : "=r"(a) : "l"(p));
    return a;
}
#define SMEM_SWIZZLE_128B(off) ((off) ^ (((off) >> 3) & 0x70))

__device__ __forceinline__ void cp_async16(uint32_t smem_addr, const void* gptr) {
    asm volatile("cp.async.cg.shared.global [%0], [%1], 16;"
                 :: "r"(smem_addr), "l"(gptr) : "memory");
}
__device__ __forceinline__ void cp_async_commit() {
    asm volatile("cp.async.commit_group;" ::: "memory");
}
template <int N>
__device__ __forceinline__ void cp_async_wait() {
    asm volatile("cp.async.wait_group %0;" :: "n"(N) : "memory");
}

__device__ __forceinline__ void ldmatrix_x4(uint32_t* r, uint32_t addr) {
    asm volatile("ldmatrix.sync.aligned.m8n8.x4.shared.b16 {%0,%1,%2,%3}, [%4];"
                 : "=r"(r[0]), "=r"(r[1]), "=r"(r[2]), "=r"(r[3]) : "r"(addr));
}
__device__ __forceinline__ void mma_s8(int* c, const uint32_t* a, const uint32_t* b) {
    asm volatile(
        "mma.sync.aligned.m16n8k32.row.col.s32.s8.s8.s32 "
        "{%0,%1,%2,%3}, {%4,%5,%6,%7}, {%8,%9}, {%0,%1,%2,%3};"
        : "+r"(c[0]), "+r"(c[1]), "+r"(c[2]), "+r"(c[3])
        : "r"(a[0]), "r"(a[1]), "r"(a[2]), "r"(a[3]), "r"(b[0]), "r"(b[1]));
}

// ---------------- init ----------------
__global__ void lstm_init_kernel() {
    int idx = blockIdx.x * blockDim.x + threadIdx.x;
    int n = 2 * 32 * 1024 / 4;
    for (int i = idx; i < n; i += gridDim.x * blockDim.x)
        ((int*)g_hq)[i] = 0;
    if (idx == 0) { g_bar = 0u; g_umax_bits = 0u; g_xmax_bits = 0u; g_wmax_bits = 0u; }
}

// ---------------- fast max|v| reduction ----------------
__global__ __launch_bounds__(256) void absmax4_kernel(
    const float4* __restrict__ p, int n4, unsigned int* outp)
{
    float m0 = 0.f, m1 = 0.f, m2 = 0.f, m3 = 0.f;
    const int stride = gridDim.x * 256;
    for (int i = blockIdx.x * 256 + threadIdx.x; i < n4; i += stride) {
        float4 v = p[i];
        m0 = fmaxf(m0, fabsf(v.x));
        m1 = fmaxf(m1, fabsf(v.y));
        m2 = fmaxf(m2, fabsf(v.z));
        m3 = fmaxf(m3, fabsf(v.w));
    }
    float m = fmaxf(fmaxf(m0, m1), fmaxf(m2, m3));
    #pragma unroll
    for (int s = 16; s > 0; s >>= 1)
        m = fmaxf(m, __shfl_xor_sync(0xFFFFFFFFu, m, s));
    __shared__ float red[8];
    if ((threadIdx.x & 31) == 0) red[threadIdx.x >> 5] = m;
    __syncthreads();
    if (threadIdx.x == 0) {
        float r = red[0];
        #pragma unroll
        for (int w = 1; w < 8; w++) r = fmaxf(r, red[w]);
        atomicMax(outp, __float_as_uint(r));
    }
}

// ---------------- quantize x -> 2-limb int8 ----------------
__global__ __launch_bounds__(256) void xq_kernel(const float* __restrict__ x) {
    size_t i = ((size_t)blockIdx.x * 256 + threadIdx.x) * 4;  // element index, k%4==0
    const float s = 127.f / fmaxf(__uint_as_float(g_xmax_bits), 1e-30f);
    float4 v = *(const float4*)(x + i);
    float vv[4] = {v.x, v.y, v.z, v.w};
    signed char q1[4], q2[4];
    #pragma unroll
    for (int j = 0; j < 4; j++) {
        float aq = vv[j] * s;
        int a1 = __float2int_rn(aq);
        a1 = max(-127, min(127, a1));
        int a2 = __float2int_rn((aq - (float)a1) * 254.f);
        q1[j] = (signed char)a1; q2[j] = (signed char)a2;
    }
    size_t m = i >> 9;
    int k = (int)(i & 511);
    int c = k >> 6, ko = k & 63;
    signed char* dst = g_xq + m * 1024 + c * 128 + ko;
    *(uchar4*)(dst)      = *(uchar4*)q1;
    *(uchar4*)(dst + 64) = *(uchar4*)q2;
}

// ---------------- fused persistent kernel: recurrence + input GEMM -------------
// 128 CTAs x 256 threads. CTA = (unit-group ug = bid>>1, batch-half bh = bid&1):
// owns 8 hidden units (32 gate cols, gate-major n = g*8+u) x 16 batches.
// Reduce phase uses ALL 256 threads: pair (2p, 2p+1) owns (b,u)=p; even lane
// sums gates i,f; odd lane sums g,o; exchange via shfl_xor(1); even lane owns
// c-state, h store. Activations are branchless single-exp-path (tanh=2sig(2x)-1).
// out[] stores deferred into the barrier bubble (not consumed cross-CTA).
// smem layout identical to R13.
#define R_H    0
#define R_X    16384
#define R_U    32768
#define R_W    65536
#define R_XW   98304
#define R_BIAS 103424
#define R_P    103552
#define REC5_SMEM_BYTES 124032
#define NCTA  128

__global__ __launch_bounds__(256, 1) void lstm_fused_kernel(
    const float* __restrict__ U, const float* __restrict__ W,
    const float* __restrict__ bias, float* __restrict__ out, int write_tail)
{
    extern __shared__ char smem[];
    const uint32_t sb = smem_to_u32(smem);
    const int tid  = threadIdx.x;
    const int wid  = tid >> 5;
    const int lane = tid & 31;
    const int u0   = (blockIdx.x >> 1) * 8;      // unit group
    const int b0   = (blockIdx.x & 1) * 16;      // batch half

    const float s_U = fmaxf(__uint_as_float(g_umax_bits), 1e-30f);
    const float s_X = fmaxf(__uint_as_float(g_xmax_bits), 1e-30f);
    const float s_W = fmaxf(__uint_as_float(g_wmax_bits), 1e-30f);
    const float uinv = 127.f / s_U;
    const float winv = 127.f / s_W;
    const float sc1  = s_U / 16129.f;            // h@U combine scales
    const float sc2  = sc1 / 254.f;
    const float sx1  = s_X * s_W / 16129.f;      // x@W combine scales
    const float sx2  = sx1 / 254.f;

    // ---- quantize U and W slices -> smem int8 2-limb, chunked+swizzled ----
    for (int i = tid; i < 32 * HID; i += 256) {
        int k = i >> 5, n = i & 31;
        int gcol = u0 + (n & 7) + 512 * (n >> 3);
        int c = k >> 6, ko = k & 63;
        uint32_t sw1 = SMEM_SWIZZLE_128B((uint32_t)(n * 128 + ko));
        uint32_t sw2 = SMEM_SWIZZLE_128B((uint32_t)(n * 128 + 64 + ko));
        {
            float v = U[(size_t)k * G4 + gcol];
            float aq = v * uinv;
            int p1 = __float2int_rn(aq);
            p1 = max(-127, min(127, p1));
            int p2 = __float2int_rn((aq - (float)p1) * 254.f);
            uint32_t base = (uint32_t)(R_U + c * 4096);
            *(signed char*)(smem + base + sw1) = (signed char)p1;
            *(signed char*)(smem + base + sw2) = (signed char)p2;
        }
        {
            float v = W[(size_t)k * G4 + gcol];
            float aq = v * winv;
            int p1 = __float2int_rn(aq);
            p1 = max(-127, min(127, p1));
            int p2 = __float2int_rn((aq - (float)p1) * 254.f);
            uint32_t base = (uint32_t)(R_W + c * 4096);
            *(signed char*)(smem + base + sw1) = (signed char)p1;
            *(signed char*)(smem + base + sw2) = (signed char)p2;
        }
    }
    if (tid < 32) {
        int gcol = u0 + (tid & 7) + 512 * (tid >> 3);
        ((float*)(smem + R_BIAS))[tid] = bias[gcol];
    }

    // ldmatrix lane address parts
    const uint32_t aRow = (uint32_t)(lane & 15);
    const uint32_t aCol = (uint32_t)(((lane >> 4) & 1) * 16);
    const uint32_t bRow = (uint32_t)(((lane >> 4) & 1) * 8 + (lane & 7));
    const uint32_t bCol = (uint32_t)(((lane >> 3) & 1) * 16);
    const uint32_t aBase = aRow * 128 + aCol;    // one m-tile (16 rows)
    const uint32_t bBase = bRow * 128 + bCol;    // n-tiles 0-1; +2048 for 2-3

    // paired reduce mapping: pair p = tid>>1 owns (b = b0+(p>>3), u = p&7)
    const int role = tid & 1;                    // 0: gates i,f; 1: gates g,o
    const int pr   = tid >> 1;
    const int rb   = pr >> 3;
    const int ua   = pr & 7;
    float c_state = 0.f;                         // valid on even lanes

    float* p_sm = (float*)(smem + R_P);
    const float* bias_sm = (const float*)(smem + R_BIAS);

    // x chunk load for step t: warp w loads chunk w (always commits a group)
    auto issue_x_chunk = [&](int t, int valid) {
        if (valid) {
            const signed char* xq = g_xq + (size_t)t * 32 * 1024;
            #pragma unroll
            for (int j = 0; j < 4; j++) {
                int idx = lane + 32 * j;
                int b = idx >> 3, seg = idx & 7;
                uint32_t sw = SMEM_SWIZZLE_128B((uint32_t)(b * 128 + seg * 16));
                cp_async16(sb + R_X + wid * 2048 + sw,
                           xq + (b0 + b) * 1024 + wid * 128 + seg * 16);
            }
        }
        cp_async_commit();
    };
    // h chunk load: warp w loads chunk w
    auto issue_h_chunk = [&](int R) {
        const signed char* hq = g_hq[R];
        #pragma unroll
        for (int j = 0; j < 4; j++) {
            int idx = lane + 32 * j;
            int b = idx >> 3, seg = idx & 7;
            uint32_t sw = SMEM_SWIZZLE_128B((uint32_t)(b * 128 + seg * 16));
            cp_async16(sb + R_H + wid * 2048 + sw,
                       hq + (b0 + b) * 1024 + wid * 128 + seg * 16);
        }
        cp_async_commit();
    };

    // xw compute for step t into slot t&1
    auto compute_xw = [&](int t) {
        int X1[4][4], X2[4][4];
        #pragma unroll
        for (int nt = 0; nt < 4; nt++)
            #pragma unroll
            for (int q = 0; q < 4; q++) { X1[nt][q] = 0; X2[nt][q] = 0; }
        const uint32_t xbse = sb + R_X + wid * 2048;
        const uint32_t wbse = sb + R_W + wid * 4096;
        #pragma unroll
        for (int kt = 0; kt < 2; kt++) {
            uint32_t aq1[4], aq2[4], bp1a[4], bp2a[4], bp1b[4], bp2b[4];
            ldmatrix_x4(aq1, xbse + SMEM_SWIZZLE_128B(aBase + kt * 32));
            ldmatrix_x4(aq2, xbse + SMEM_SWIZZLE_128B(aBase + 64 + kt * 32));
            ldmatrix_x4(bp1a, wbse + SMEM_SWIZZLE_128B(bBase + kt * 32));
            ldmatrix_x4(bp2a, wbse + SMEM_SWIZZLE_128B(bBase + 64 + kt * 32));
            ldmatrix_x4(bp1b, wbse + 2048 + SMEM_SWIZZLE_128B(bBase + kt * 32));
            ldmatrix_x4(bp2b, wbse + 2048 + SMEM_SWIZZLE_128B(bBase + 64 + kt * 32));
            #pragma unroll
            for (int nt = 0; nt < 4; nt++) {
                uint32_t* b1 = (nt < 2) ? &bp1a[(nt & 1) * 2] : &bp1b[(nt & 1) * 2];
                uint32_t* b2 = (nt < 2) ? &bp2a[(nt & 1) * 2] : &bp2b[(nt & 1) * 2];
                mma_s8(X1[nt], aq1, b1);
                mma_s8(X2[nt], aq1, b2);
                mma_s8(X2[nt], aq2, b1);
            }
        }
        {
            const int m  = lane >> 2;
            const int nn = 2 * (lane & 3);
            #pragma unroll
            for (int nt = 0; nt < 4; nt++) {
                int col = nt * 8 + nn;
                float e0 = (float)X1[nt][0] * sx1 + (float)X2[nt][0] * sx2;
                float e1 = (float)X1[nt][1] * sx1 + (float)X2[nt][1] * sx2;
                float e2 = (float)X1[nt][2] * sx1 + (float)X2[nt][2] * sx2;
                float e3 = (float)X1[nt][3] * sx1 + (float)X2[nt][3] * sx2;
                *(float2*)&p_sm[(wid * 16 + m) * 40 + col]     = make_float2(e0, e1);
                *(float2*)&p_sm[(wid * 16 + m + 8) * 40 + col] = make_float2(e2, e3);
            }
        }
        __syncthreads();   // xw partials visible
        if (tid < 128) {
            int n = tid & 31;
            int bq = (tid >> 5) * 4;
            float* dst = (float*)(smem + R_XW + (uint32_t)((t & 1) * 2560));
            #pragma unroll
            for (int bi = 0; bi < 4; bi++) {
                int b = bq + bi;
                float v = bias_sm[n];
                #pragma unroll
                for (int w = 0; w < 8; w++)
                    v += p_sm[(w * 16 + b) * 40 + n];
                dst[n * 20 + b] = v;
            }
        }
    };

    __syncthreads();            // U/W slices + bias ready

    // ---- prologue: xw(0) into slot 0 ----
    issue_x_chunk(0, 1);
    cp_async_wait<0>();
    compute_xw(0);
    __syncthreads();            // xw(0) ready (and p_sm free)

    for (int t = 0; t < T_STEPS; t++) {
        const int R = t & 1;

        issue_h_chunk(R);                     // group: h(t) chunk w
        issue_x_chunk(t + 1, t + 1 < T_STEPS);// group: x(t+1) (maybe empty)
        cp_async_wait<1>();                   // h ready (x pending)

        // ---- h @ U ----
        int C1[4][4], C2[4][4];
        #pragma unroll
        for (int nt = 0; nt < 4; nt++)
            #pragma unroll
            for (int q = 0; q < 4; q++) { C1[nt][q] = 0; C2[nt][q] = 0; }

        const uint32_t hbse = sb + R_H + wid * 2048;
        const uint32_t ubse = sb + R_U + wid * 4096;
        #pragma unroll
        for (int kt = 0; kt < 2; kt++) {
            uint32_t aq1[4], aq2[4], bp1a[4], bp2a[4], bp1b[4], bp2b[4];
            ldmatrix_x4(aq1, hbse + SMEM_SWIZZLE_128B(aBase + kt * 32));
            ldmatrix_x4(aq2, hbse + SMEM_SWIZZLE_128B(aBase + 64 + kt * 32));
            ldmatrix_x4(bp1a, ubse + SMEM_SWIZZLE_128B(bBase + kt * 32));
            ldmatrix_x4(bp2a, ubse + SMEM_SWIZZLE_128B(bBase + 64 + kt * 32));
            ldmatrix_x4(bp1b, ubse + 2048 + SMEM_SWIZZLE_128B(bBase + kt * 32));
            ldmatrix_x4(bp2b, ubse + 2048 + SMEM_SWIZZLE_128B(bBase + 64 + kt * 32));
            #pragma unroll
            for (int nt = 0; nt < 4; nt++) {
                uint32_t* b1 = (nt < 2) ? &bp1a[(nt & 1) * 2] : &bp1b[(nt & 1) * 2];
                uint32_t* b2 = (nt < 2) ? &bp2a[(nt & 1) * 2] : &bp2b[(nt & 1) * 2];
                mma_s8(C1[nt], aq1, b1);
                mma_s8(C2[nt], aq1, b2);
                mma_s8(C2[nt], aq2, b1);
            }
        }
        {
            const int m  = lane >> 2;
            const int nn = 2 * (lane & 3);
            #pragma unroll
            for (int nt = 0; nt < 4; nt++) {
                int col = nt * 8 + nn;
                float e0 = (float)C1[nt][0] * sc1 + (float)C2[nt][0] * sc2;
                float e1 = (float)C1[nt][1] * sc1 + (float)C2[nt][1] * sc2;
                float e2 = (float)C1[nt][2] * sc1 + (float)C2[nt][2] * sc2;
                float e3 = (float)C1[nt][3] * sc1 + (float)C2[nt][3] * sc2;
                *(float2*)&p_sm[(wid * 16 + m) * 40 + col]     = make_float2(e0, e1);
                *(float2*)&p_sm[(wid * 16 + m + 8) * 40 + col] = make_float2(e2, e3);
            }
        }
        __syncthreads();   // h partials + xw(t) visible

        // ---- paired reduce + activations (ALL 256 threads) ----
        float h_keep = 0.f, c_keep = 0.f;
        {
            const float* xw_sm = (const float*)(smem + R_XW + (uint32_t)((t & 1) * 2560));
            const int nA = role ? 16 + ua : ua;        // g : i
            const int nB = role ? 24 + ua : 8 + ua;    // o : f
            float sA = xw_sm[nA * 20 + rb];
            float sB = xw_sm[nB * 20 + rb];
            #pragma unroll
            for (int w = 0; w < 8; w++) {
                sA += p_sm[(w * 16 + rb) * 40 + nA];
                sB += p_sm[(w * 16 + rb) * 40 + nB];
            }
            // branchless: role 0 -> eA = sig(sA); role 1 -> eA = tanh(sA)=2sig(2sA)-1
            float xA = role ? 2.f * sA : sA;
            float sgA = 1.f / (1.f + __expf(-xA));
            float eA = role ? 2.f * sgA - 1.f : sgA;   // ig | gg
            float eB = 1.f / (1.f + __expf(-sB));      // fg | og
            float gg = __shfl_xor_sync(0xFFFFFFFFu, eA, 1);
            float og = __shfl_xor_sync(0xFFFFFFFFu, eB, 1);
            if (!role) {
                float cnew = eB * c_state + eA * gg;
                float th = 2.f / (1.f + __expf(-2.f * cnew)) - 1.f;
                float hnew = og * th;
                c_state = cnew;
                h_keep = hnew; c_keep = cnew;

                // critical-path store: quantized h for next step's consumers
                float aq = hnew * 127.f;
                int q1 = __float2int_rn(aq);
                q1 = max(-127, min(127, q1));
                int q2 = __float2int_rn((aq - (float)q1) * 254.f);
                int uu = u0 + ua;
                int cc2 = uu >> 6, ko = uu & 63;
                signed char* dst = g_hq[R ^ 1] + (b0 + rb) * 1024 + cc2 * 128 + ko;
                dst[0]  = (signed char)q1;
                dst[64] = (signed char)q2;
            }
        }
        __syncthreads();   // h stores + p_sm/xw reads complete

        if (t + 1 < T_STEPS) {
            // release EARLY: consumers can start while we do deferred work
            if (tid == 0) {
                asm volatile("red.release.gpu.add.u32 [%0], %1;"
                             :: "l"(&g_bar), "r"(1u) : "memory");
            }
            // deferred out store (not consumed cross-CTA)
            if (!role)
                out[((size_t)t * BATCH + b0 + rb) * HID + u0 + ua] = h_keep;
            // ---- x(t+1) @ W in the barrier bubble ----
            cp_async_wait<0>();   // x(t+1) ready
            compute_xw(t + 1);
            // ---- poll barrier ----
            if (tid == 0) {
                unsigned int target = (unsigned int)NCTA * (unsigned int)(t + 1);
                unsigned int v;
                do {
                    asm volatile("ld.acquire.gpu.u32 %0, [%1];"
                                 : "=r"(v) : "l"(&g_bar) : "memory");
                } while (v < target);
            }
            __syncthreads();      // orders fold reads before next-step p_sm writes
        } else {
            // last step: out + tail
            if (!role) {
                const int b = b0 + rb;
                out[((size_t)t * BATCH + b) * HID + u0 + ua] = h_keep;
                if (write_tail) {
                    out[(size_t)T_STEPS * BATCH * HID + (size_t)b * HID + u0 + ua] = h_keep;
                    out[(size_t)T_STEPS * BATCH * HID + BATCH * HID
                        + (size_t)b * HID + u0 + ua] = c_keep;
                }
            }
        }
    }
}

// ---------------- launch ----------------
extern "C" void kernel_launch(void* const* d_in, const int* in_sizes, int n_in,
                              void* d_out, int out_size)
{
    const float* x    = (const float*)d_in[0]; // (T,B,I)
    const float* W    = (const float*)d_in[1]; // (I,4H)
    const float* U    = (const float*)d_in[2]; // (H,4H)
    const float* bias = (const float*)d_in[3]; // (4H,)
    float* out = (float*)d_out;

    const long long need_tail = (long long)T_STEPS * BATCH * HID + 2LL * BATCH * HID;
    int write_tail = ((long long)out_size >= need_tail) ? 1 : 0;

    static int configured = 0;
    if (!configured) {
        cudaFuncSetAttribute(lstm_fused_kernel,
                             cudaFuncAttributeMaxDynamicSharedMemorySize,
                             REC5_SMEM_BYTES);
        configured = 1;
    }

    unsigned int* d_umax;
    unsigned int* d_xmax;
    unsigned int* d_wmax;
    cudaGetSymbolAddress((void**)&d_umax, g_umax_bits);
    cudaGetSymbolAddress((void**)&d_xmax, g_xmax_bits);
    cudaGetSymbolAddress((void**)&d_wmax, g_wmax_bits);

    lstm_init_kernel<<<64, 256>>>();
    absmax4_kernel<<<512, 256>>>((const float4*)U, HID * G4 / 4, d_umax);
    absmax4_kernel<<<512, 256>>>((const float4*)W, INP * G4 / 4, d_wmax);
    absmax4_kernel<<<1024, 256>>>((const float4*)x, MTOT * INP / 4, d_xmax);
    xq_kernel<<<(MTOT * INP) / 4 / 256, 256>>>(x);
    lstm_fused_kernel<<<NCTA, 256, REC5_SMEM_BYTES>>>(U, W, bias, out, write_tail);
}

// round 15
// speedup vs baseline: 1.0255x; 1.0255x over previous
#include <cuda_runtime.h>
#include <cuda_bf16.h>
#include <math.h>
#include <stdint.h>

#define T_STEPS 1024
#define BATCH   32
#define INP     512
#define HID     512
#define G4      2048   // 4*HID
#define MTOT    (T_STEPS * BATCH)   // 32768

// ---------------- scratch ----------------
__device__ signed char g_xq[(size_t)MTOT * 1024];    // x 2-limb int8 [m][c*128+limb*64+ko]
__device__ signed char g_hq[2][32 * 1024];           // h 2-limb int8 ping-pong
__device__ unsigned int g_bar;                       // grid barrier counter
__device__ unsigned int g_umax_bits;                 // max|U|
__device__ unsigned int g_xmax_bits;                 // max|x|
__device__ unsigned int g_wmax_bits;                 // max|W|

// ================= helpers =================
__device__ __forceinline__ uint32_t smem_to_u32(const void* p) {
    uint32_t a;
    asm("{ .reg .u64 t; cvta.to.shared.u64 t, %1; cvt.u32.u64 %0, t; }"
        : "=r"(a) : "l"(p));
    return a;
}
#define SMEM_SWIZZLE_128B(off) ((off) ^ (((off) >> 3) & 0x70))

__device__ __forceinline__ void cp_async16(uint32_t smem_addr, const void* gptr) {
    asm volatile("cp.async.cg.shared.global [%0], [%1], 16;"
                 :: "r"(smem_addr), "l"(gptr) : "memory");
}
__device__ __forceinline__ void cp_async_commit() {
    asm volatile("cp.async.commit_group;" ::: "memory");
}
template <int N>
__device__ __forceinline__ void cp_async_wait() {
    asm volatile("cp.async.wait_group %0;" :: "n"(N) : "memory");
}

__device__ __forceinline__ void ldmatrix_x4(uint32_t* r, uint32_t addr) {
    asm volatile("ldmatrix.sync.aligned.m8n8.x4.shared.b16 {%0,%1,%2,%3}, [%4];"
                 : "=r"(r[0]), "=r"(r[1]), "=r"(r[2]), "=r"(r[3]) : "r"(addr));
}
__device__ __forceinline__ void mma_s8(int* c, const uint32_t* a, const uint32_t* b) {
    asm volatile(
        "mma.sync.aligned.m16n8k32.row.col.s32.s8.s8.s32 "
        "{%0,%1,%2,%3}, {%4,%5,%6,%7}, {%8,%9}, {%0,%1,%2,%3};"
        : "+r"(c[0]), "+r"(c[1]), "+r"(c[2]), "+r"(c[3])
        : "r"(a[0]), "r"(a[1]), "r"(a[2]), "r"(a[3]), "r"(b[0]), "r"(b[1]));
}
__device__ __forceinline__ float sigmoidf_(float v) {
    return 1.f / (1.f + __expf(-v));
}
__device__ __forceinline__ float tanhf_fast(float v) {
    return 2.f / (1.f + __expf(-2.f * v)) - 1.f;
}

// ---------------- init ----------------
__global__ void lstm_init_kernel() {
    int idx = blockIdx.x * blockDim.x + threadIdx.x;
    int n = 2 * 32 * 1024 / 4;
    for (int i = idx; i < n; i += gridDim.x * blockDim.x)
        ((int*)g_hq)[i] = 0;
    if (idx == 0) { g_bar = 0u; g_umax_bits = 0u; g_xmax_bits = 0u; g_wmax_bits = 0u; }
}

// ---------------- fast max|v| reduction ----------------
__global__ __launch_bounds__(256) void absmax4_kernel(
    const float4* __restrict__ p, int n4, unsigned int* outp)
{
    float m0 = 0.f, m1 = 0.f, m2 = 0.f, m3 = 0.f;
    const int stride = gridDim.x * 256;
    for (int i = blockIdx.x * 256 + threadIdx.x; i < n4; i += stride) {
        float4 v = p[i];
        m0 = fmaxf(m0, fabsf(v.x));
        m1 = fmaxf(m1, fabsf(v.y));
        m2 = fmaxf(m2, fabsf(v.z));
        m3 = fmaxf(m3, fabsf(v.w));
    }
    float m = fmaxf(fmaxf(m0, m1), fmaxf(m2, m3));
    #pragma unroll
    for (int s = 16; s > 0; s >>= 1)
        m = fmaxf(m, __shfl_xor_sync(0xFFFFFFFFu, m, s));
    __shared__ float red[8];
    if ((threadIdx.x & 31) == 0) red[threadIdx.x >> 5] = m;
    __syncthreads();
    if (threadIdx.x == 0) {
        float r = red[0];
        #pragma unroll
        for (int w = 1; w < 8; w++) r = fmaxf(r, red[w]);
        atomicMax(outp, __float_as_uint(r));
    }
}

// ---------------- quantize x -> 2-limb int8 ----------------
__global__ __launch_bounds__(256) void xq_kernel(const float* __restrict__ x) {
    size_t i = ((size_t)blockIdx.x * 256 + threadIdx.x) * 4;  // element index, k%4==0
    const float s = 127.f / fmaxf(__uint_as_float(g_xmax_bits), 1e-30f);
    float4 v = *(const float4*)(x + i);
    float vv[4] = {v.x, v.y, v.z, v.w};
    signed char q1[4], q2[4];
    #pragma unroll
    for (int j = 0; j < 4; j++) {
        float aq = vv[j] * s;
        int a1 = __float2int_rn(aq);
        a1 = max(-127, min(127, a1));
        int a2 = __float2int_rn((aq - (float)a1) * 254.f);
        q1[j] = (signed char)a1; q2[j] = (signed char)a2;
    }
    size_t m = i >> 9;
    int k = (int)(i & 511);
    int c = k >> 6, ko = k & 63;
    signed char* dst = g_xq + m * 1024 + c * 128 + ko;
    *(uchar4*)(dst)      = *(uchar4*)q1;
    *(uchar4*)(dst + 64) = *(uchar4*)q2;
}

// ---------------- fused persistent kernel: recurrence + input GEMM -------------
// (R13 structure. Changes vs R13: fast tanh on the serial chain; out[] store
//  deferred into the barrier bubble. Everything else identical.)
#define R_H    0
#define R_X    16384
#define R_U    32768
#define R_W    65536
#define R_XW   98304
#define R_BIAS 103424
#define R_P    103552
#define REC5_SMEM_BYTES 124032
#define NCTA  128

__global__ __launch_bounds__(256, 1) void lstm_fused_kernel(
    const float* __restrict__ U, const float* __restrict__ W,
    const float* __restrict__ bias, float* __restrict__ out, int write_tail)
{
    extern __shared__ char smem[];
    const uint32_t sb = smem_to_u32(smem);
    const int tid  = threadIdx.x;
    const int wid  = tid >> 5;
    const int lane = tid & 31;
    const int u0   = (blockIdx.x >> 1) * 8;      // unit group
    const int b0   = (blockIdx.x & 1) * 16;      // batch half

    const float s_U = fmaxf(__uint_as_float(g_umax_bits), 1e-30f);
    const float s_X = fmaxf(__uint_as_float(g_xmax_bits), 1e-30f);
    const float s_W = fmaxf(__uint_as_float(g_wmax_bits), 1e-30f);
    const float uinv = 127.f / s_U;
    const float winv = 127.f / s_W;
    const float sc1  = s_U / 16129.f;            // h@U combine scales
    const float sc2  = sc1 / 254.f;
    const float sx1  = s_X * s_W / 16129.f;      // x@W combine scales
    const float sx2  = sx1 / 254.f;

    // ---- quantize U and W slices -> smem int8 2-limb, chunked+swizzled ----
    for (int i = tid; i < 32 * HID; i += 256) {
        int k = i >> 5, n = i & 31;
        int gcol = u0 + (n & 7) + 512 * (n >> 3);
        int c = k >> 6, ko = k & 63;
        uint32_t sw1 = SMEM_SWIZZLE_128B((uint32_t)(n * 128 + ko));
        uint32_t sw2 = SMEM_SWIZZLE_128B((uint32_t)(n * 128 + 64 + ko));
        {
            float v = U[(size_t)k * G4 + gcol];
            float aq = v * uinv;
            int p1 = __float2int_rn(aq);
            p1 = max(-127, min(127, p1));
            int p2 = __float2int_rn((aq - (float)p1) * 254.f);
            uint32_t base = (uint32_t)(R_U + c * 4096);
            *(signed char*)(smem + base + sw1) = (signed char)p1;
            *(signed char*)(smem + base + sw2) = (signed char)p2;
        }
        {
            float v = W[(size_t)k * G4 + gcol];
            float aq = v * winv;
            int p1 = __float2int_rn(aq);
            p1 = max(-127, min(127, p1));
            int p2 = __float2int_rn((aq - (float)p1) * 254.f);
            uint32_t base = (uint32_t)(R_W + c * 4096);
            *(signed char*)(smem + base + sw1) = (signed char)p1;
            *(signed char*)(smem + base + sw2) = (signed char)p2;
        }
    }
    if (tid < 32) {
        int gcol = u0 + (tid & 7) + 512 * (tid >> 3);
        ((float*)(smem + R_BIAS))[tid] = bias[gcol];
    }

    // ldmatrix lane address parts
    const uint32_t aRow = (uint32_t)(lane & 15);
    const uint32_t aCol = (uint32_t)(((lane >> 4) & 1) * 16);
    const uint32_t bRow = (uint32_t)(((lane >> 4) & 1) * 8 + (lane & 7));
    const uint32_t bCol = (uint32_t)(((lane >> 3) & 1) * 16);
    const uint32_t aBase = aRow * 128 + aCol;    // one m-tile (16 rows)
    const uint32_t bBase = bRow * 128 + bCol;    // n-tiles 0-1; +2048 for 2-3

    // activation mapping: thread (tid<128) owns (b = b0 + (tid>>3), u = tid&7)
    const int rb = tid >> 3;
    const int ua = tid & 7;
    float c_state = 0.f;

    float* p_sm = (float*)(smem + R_P);
    const float* bias_sm = (const float*)(smem + R_BIAS);

    // x chunk load for step t: warp w loads chunk w (always commits a group)
    auto issue_x_chunk = [&](int t, int valid) {
        if (valid) {
            const signed char* xq = g_xq + (size_t)t * 32 * 1024;
            #pragma unroll
            for (int j = 0; j < 4; j++) {
                int idx = lane + 32 * j;
                int b = idx >> 3, seg = idx & 7;
                uint32_t sw = SMEM_SWIZZLE_128B((uint32_t)(b * 128 + seg * 16));
                cp_async16(sb + R_X + wid * 2048 + sw,
                           xq + (b0 + b) * 1024 + wid * 128 + seg * 16);
            }
        }
        cp_async_commit();
    };
    // h chunk load: warp w loads chunk w
    auto issue_h_chunk = [&](int R) {
        const signed char* hq = g_hq[R];
        #pragma unroll
        for (int j = 0; j < 4; j++) {
            int idx = lane + 32 * j;
            int b = idx >> 3, seg = idx & 7;
            uint32_t sw = SMEM_SWIZZLE_128B((uint32_t)(b * 128 + seg * 16));
            cp_async16(sb + R_H + wid * 2048 + sw,
                       hq + (b0 + b) * 1024 + wid * 128 + seg * 16);
        }
        cp_async_commit();
    };

    // xw compute for step t into slot t&1: A = x buffer chunk w, B = W chunk w
    auto compute_xw = [&](int t) {
        int X1[4][4], X2[4][4];
        #pragma unroll
        for (int nt = 0; nt < 4; nt++)
            #pragma unroll
            for (int q = 0; q < 4; q++) { X1[nt][q] = 0; X2[nt][q] = 0; }
        const uint32_t xbse = sb + R_X + wid * 2048;
        const uint32_t wbse = sb + R_W + wid * 4096;
        #pragma unroll
        for (int kt = 0; kt < 2; kt++) {
            uint32_t aq1[4], aq2[4], bp1a[4], bp2a[4], bp1b[4], bp2b[4];
            ldmatrix_x4(aq1, xbse + SMEM_SWIZZLE_128B(aBase + kt * 32));
            ldmatrix_x4(aq2, xbse + SMEM_SWIZZLE_128B(aBase + 64 + kt * 32));
            ldmatrix_x4(bp1a, wbse + SMEM_SWIZZLE_128B(bBase + kt * 32));
            ldmatrix_x4(bp2a, wbse + SMEM_SWIZZLE_128B(bBase + 64 + kt * 32));
            ldmatrix_x4(bp1b, wbse + 2048 + SMEM_SWIZZLE_128B(bBase + kt * 32));
            ldmatrix_x4(bp2b, wbse + 2048 + SMEM_SWIZZLE_128B(bBase + 64 + kt * 32));
            #pragma unroll
            for (int nt = 0; nt < 4; nt++) {
                uint32_t* b1 = (nt < 2) ? &bp1a[(nt & 1) * 2] : &bp1b[(nt & 1) * 2];
                uint32_t* b2 = (nt < 2) ? &bp2a[(nt & 1) * 2] : &bp2b[(nt & 1) * 2];
                mma_s8(X1[nt], aq1, b1);
                mma_s8(X2[nt], aq1, b2);
                mma_s8(X2[nt], aq2, b1);
            }
        }
        {
            const int m  = lane >> 2;
            const int nn = 2 * (lane & 3);
            #pragma unroll
            for (int nt = 0; nt < 4; nt++) {
                int col = nt * 8 + nn;
                float e0 = (float)X1[nt][0] * sx1 + (float)X2[nt][0] * sx2;
                float e1 = (float)X1[nt][1] * sx1 + (float)X2[nt][1] * sx2;
                float e2 = (float)X1[nt][2] * sx1 + (float)X2[nt][2] * sx2;
                float e3 = (float)X1[nt][3] * sx1 + (float)X2[nt][3] * sx2;
                *(float2*)&p_sm[(wid * 16 + m) * 40 + col]     = make_float2(e0, e1);
                *(float2*)&p_sm[(wid * 16 + m + 8) * 40 + col] = make_float2(e2, e3);
            }
        }
        __syncthreads();   // xw partials visible
        // fold + bias -> xw_sm slot t&1 (conflict-free reads: n = lane)
        if (tid < 128) {
            int n = tid & 31;
            int bq = (tid >> 5) * 4;
            float* dst = (float*)(smem + R_XW + (uint32_t)((t & 1) * 2560));
            #pragma unroll
            for (int bi = 0; bi < 4; bi++) {
                int b = bq + bi;
                float v = bias_sm[n];
                #pragma unroll
                for (int w = 0; w < 8; w++)
                    v += p_sm[(w * 16 + b) * 40 + n];
                dst[n * 20 + b] = v;
            }
        }
    };

    __syncthreads();            // U/W slices + bias ready

    // ---- prologue: xw(0) into slot 0 ----
    issue_x_chunk(0, 1);
    cp_async_wait<0>();
    compute_xw(0);
    __syncthreads();            // xw(0) ready (and p_sm free)

    for (int t = 0; t < T_STEPS; t++) {
        const int R = t & 1;

        issue_h_chunk(R);                     // group: h(t) chunk w
        issue_x_chunk(t + 1, t + 1 < T_STEPS);// group: x(t+1) (maybe empty)
        cp_async_wait<1>();                   // h ready (x pending)

        // ---- h @ U ----
        int C1[4][4], C2[4][4];
        #pragma unroll
        for (int nt = 0; nt < 4; nt++)
            #pragma unroll
            for (int q = 0; q < 4; q++) { C1[nt][q] = 0; C2[nt][q] = 0; }

        const uint32_t hbse = sb + R_H + wid * 2048;
        const uint32_t ubse = sb + R_U + wid * 4096;
        #pragma unroll
        for (int kt = 0; kt < 2; kt++) {
            uint32_t aq1[4], aq2[4], bp1a[4], bp2a[4], bp1b[4], bp2b[4];
            ldmatrix_x4(aq1, hbse + SMEM_SWIZZLE_128B(aBase + kt * 32));
            ldmatrix_x4(aq2, hbse + SMEM_SWIZZLE_128B(aBase + 64 + kt * 32));
            ldmatrix_x4(bp1a, ubse + SMEM_SWIZZLE_128B(bBase + kt * 32));
            ldmatrix_x4(bp2a, ubse + SMEM_SWIZZLE_128B(bBase + 64 + kt * 32));
            ldmatrix_x4(bp1b, ubse + 2048 + SMEM_SWIZZLE_128B(bBase + kt * 32));
            ldmatrix_x4(bp2b, ubse + 2048 + SMEM_SWIZZLE_128B(bBase + 64 + kt * 32));
            #pragma unroll
            for (int nt = 0; nt < 4; nt++) {
                uint32_t* b1 = (nt < 2) ? &bp1a[(nt & 1) * 2] : &bp1b[(nt & 1) * 2];
                uint32_t* b2 = (nt < 2) ? &bp2a[(nt & 1) * 2] : &bp2b[(nt & 1) * 2];
                mma_s8(C1[nt], aq1, b1);
                mma_s8(C2[nt], aq1, b2);
                mma_s8(C2[nt], aq2, b1);
            }
        }
        {
            const int m  = lane >> 2;
            const int nn = 2 * (lane & 3);
            #pragma unroll
            for (int nt = 0; nt < 4; nt++) {
                int col = nt * 8 + nn;
                float e0 = (float)C1[nt][0] * sc1 + (float)C2[nt][0] * sc2;
                float e1 = (float)C1[nt][1] * sc1 + (float)C2[nt][1] * sc2;
                float e2 = (float)C1[nt][2] * sc1 + (float)C2[nt][2] * sc2;
                float e3 = (float)C1[nt][3] * sc1 + (float)C2[nt][3] * sc2;
                *(float2*)&p_sm[(wid * 16 + m) * 40 + col]     = make_float2(e0, e1);
                *(float2*)&p_sm[(wid * 16 + m + 8) * 40 + col] = make_float2(e2, e3);
            }
        }
        __syncthreads();   // h partials + xw(t) visible

        // ---- reduce + activations (tid < 128): thread owns (rb, ua) ----
        float h_keep = 0.f, c_keep = 0.f;
        if (tid < 128) {
            const float* xw_sm = (const float*)(smem + R_XW + (uint32_t)((t & 1) * 2560));
            float s[4];
            #pragma unroll
            for (int g = 0; g < 4; g++) {
                int n = g * 8 + ua;
                float v = xw_sm[n * 20 + rb];
                #pragma unroll
                for (int w = 0; w < 8; w++)
                    v += p_sm[(w * 16 + rb) * 40 + n];
                s[g] = v;
            }
            float ig = sigmoidf_(s[0]);
            float fg = sigmoidf_(s[1]);
            float gg = tanhf_fast(s[2]);
            float og = sigmoidf_(s[3]);
            float cnew = fg * c_state + ig * gg;
            float hnew = og * tanhf_fast(cnew);
            c_state = cnew;
            h_keep = hnew; c_keep = cnew;

            // critical-path store: quantized h for next step's consumers
            float aq = hnew * 127.f;
            int q1 = __float2int_rn(aq);
            q1 = max(-127, min(127, q1));
            int q2 = __float2int_rn((aq - (float)q1) * 254.f);
            int uu = u0 + ua;
            int cc2 = uu >> 6, ko = uu & 63;
            signed char* dst = g_hq[R ^ 1] + (b0 + rb) * 1024 + cc2 * 128 + ko;
            dst[0]  = (signed char)q1;
            dst[64] = (signed char)q2;
        }
        __syncthreads();   // h stores + p_sm/xw reads complete

        if (t + 1 < T_STEPS) {
            // release EARLY: consumers can start while we compute xw(t+1)
            if (tid == 0) {
                asm volatile("red.release.gpu.add.u32 [%0], %1;"
                             :: "l"(&g_bar), "r"(1u) : "memory");
            }
            // deferred out store (not consumed cross-CTA)
            if (tid < 128)
                out[((size_t)t * BATCH + b0 + rb) * HID + u0 + ua] = h_keep;
            // ---- x(t+1) @ W in the barrier bubble ----
            cp_async_wait<0>();   // x(t+1) ready
            compute_xw(t + 1);
            // ---- poll barrier ----
            if (tid == 0) {
                unsigned int target = (unsigned int)NCTA * (unsigned int)(t + 1);
                unsigned int v;
                do {
                    asm volatile("ld.acquire.gpu.u32 %0, [%1];"
                                 : "=r"(v) : "l"(&g_bar) : "memory");
                } while (v < target);
            }
            __syncthreads();      // orders fold reads before next-step p_sm writes
        } else {
            if (tid < 128) {
                const int b = b0 + rb;
                out[((size_t)t * BATCH + b) * HID + u0 + ua] = h_keep;
                if (write_tail) {
                    out[(size_t)T_STEPS * BATCH * HID + (size_t)b * HID + u0 + ua] = h_keep;
                    out[(size_t)T_STEPS * BATCH * HID + BATCH * HID
                        + (size_t)b * HID + u0 + ua] = c_keep;
                }
            }
        }
    }
}

// ---------------- launch ----------------
extern "C" void kernel_launch(void* const* d_in, const int* in_sizes, int n_in,
                              void* d_out, int out_size)
{
    const float* x    = (const float*)d_in[0]; // (T,B,I)
    const float* W    = (const float*)d_in[1]; // (I,4H)
    const float* U    = (const float*)d_in[2]; // (H,4H)
    const float* bias = (const float*)d_in[3]; // (4H,)
    float* out = (float*)d_out;

    const long long need_tail = (long long)T_STEPS * BATCH * HID + 2LL * BATCH * HID;
    int write_tail = ((long long)out_size >= need_tail) ? 1 : 0;

    static int configured = 0;
    if (!configured) {
        cudaFuncSetAttribute(lstm_fused_kernel,
                             cudaFuncAttributeMaxDynamicSharedMemorySize,
                             REC5_SMEM_BYTES);
        configured = 1;
    }

    unsigned int* d_umax;
    unsigned int* d_xmax;
    unsigned int* d_wmax;
    cudaGetSymbolAddress((void**)&d_umax, g_umax_bits);
    cudaGetSymbolAddress((void**)&d_xmax, g_xmax_bits);
    cudaGetSymbolAddress((void**)&d_wmax, g_wmax_bits);

    lstm_init_kernel<<<64, 256>>>();
    absmax4_kernel<<<512, 256>>>((const float4*)U, HID * G4 / 4, d_umax);
    absmax4_kernel<<<512, 256>>>((const float4*)W, INP * G4 / 4, d_wmax);
    absmax4_kernel<<<1024, 256>>>((const float4*)x, MTOT * INP / 4, d_xmax);
    xq_kernel<<<(MTOT * INP) / 4 / 256, 256>>>(x);
    lstm_fused_kernel<<<NCTA, 256, REC5_SMEM_BYTES>>>(U, W, bias, out, write_tail);
}

// round 16
// speedup vs baseline: 1.0517x; 1.0256x over previous
#include <cuda_runtime.h>
#include <cuda_bf16.h>
#include <math.h>
#include <stdint.h>

#define T_STEPS 1024
#define BATCH   32
#define INP     512
#define HID     512
#define G4      2048   // 4*HID
#define MTOT    (T_STEPS * BATCH)   // 32768

// ---------------- scratch ----------------
__device__ signed char g_xq[(size_t)MTOT * 1024];    // x 2-limb int8 [m][c*128+limb*64+ko]
__device__ signed char g_hq[2][32 * 1024];           // h 2-limb int8 ping-pong
__device__ unsigned int g_bar;                       // grid barrier counter
__device__ unsigned int g_umax_bits;                 // max|U|
__device__ unsigned int g_xmax_bits;                 // max|x|
__device__ unsigned int g_wmax_bits;                 // max|W|

// ================= helpers =================
__device__ __forceinline__ uint32_t smem_to_u32(const void* p) {
    uint32_t a;
    asm("{ .reg .u64 t; cvta.to.shared.u64 t, %1; cvt.u32.u64 %0, t; }"
        : "=r"(a) : "l"(p));
    return a;
}
#define SMEM_SWIZZLE_128B(off) ((off) ^ (((off) >> 3) & 0x70))

__device__ __forceinline__ void cp_async16(uint32_t smem_addr, const void* gptr) {
    asm volatile("cp.async.cg.shared.global [%0], [%1], 16;"
                 :: "r"(smem_addr), "l"(gptr) : "memory");
}
__device__ __forceinline__ void cp_async_commit() {
    asm volatile("cp.async.commit_group;" ::: "memory");
}
template <int N>
__device__ __forceinline__ void cp_async_wait() {
    asm volatile("cp.async.wait_group %0;" :: "n"(N) : "memory");
}

__device__ __forceinline__ void ldmatrix_x4(uint32_t* r, uint32_t addr) {
    asm volatile("ldmatrix.sync.aligned.m8n8.x4.shared.b16 {%0,%1,%2,%3}, [%4];"
                 : "=r"(r[0]), "=r"(r[1]), "=r"(r[2]), "=r"(r[3]) : "r"(addr));
}
__device__ __forceinline__ void mma_s8(int* c, const uint32_t* a, const uint32_t* b) {
    asm volatile(
        "mma.sync.aligned.m16n8k32.row.col.s32.s8.s8.s32 "
        "{%0,%1,%2,%3}, {%4,%5,%6,%7}, {%8,%9}, {%0,%1,%2,%3};"
        : "+r"(c[0]), "+r"(c[1]), "+r"(c[2]), "+r"(c[3])
        : "r"(a[0]), "r"(a[1]), "r"(a[2]), "r"(a[3]), "r"(b[0]), "r"(b[1]));
}
__device__ __forceinline__ float sigmoidf_(float v) {
    return 1.f / (1.f + __expf(-v));
}
__device__ __forceinline__ float tanhf_fast(float v) {
    return 2.f / (1.f + __expf(-2.f * v)) - 1.f;
}

// ---------------- init ----------------
__global__ void lstm_init_kernel() {
    int idx = blockIdx.x * blockDim.x + threadIdx.x;
    int n = 2 * 32 * 1024 / 4;
    for (int i = idx; i < n; i += gridDim.x * blockDim.x)
        ((int*)g_hq)[i] = 0;
    if (idx == 0) { g_bar = 0u; g_umax_bits = 0u; g_xmax_bits = 0u; g_wmax_bits = 0u; }
}

// ---------------- fast max|v| reduction ----------------
__global__ __launch_bounds__(256) void absmax4_kernel(
    const float4* __restrict__ p, int n4, unsigned int* outp)
{
    float m0 = 0.f, m1 = 0.f, m2 = 0.f, m3 = 0.f;
    const int stride = gridDim.x * 256;
    for (int i = blockIdx.x * 256 + threadIdx.x; i < n4; i += stride) {
        float4 v = p[i];
        m0 = fmaxf(m0, fabsf(v.x));
        m1 = fmaxf(m1, fabsf(v.y));
        m2 = fmaxf(m2, fabsf(v.z));
        m3 = fmaxf(m3, fabsf(v.w));
    }
    float m = fmaxf(fmaxf(m0, m1), fmaxf(m2, m3));
    #pragma unroll
    for (int s = 16; s > 0; s >>= 1)
        m = fmaxf(m, __shfl_xor_sync(0xFFFFFFFFu, m, s));
    __shared__ float red[8];
    if ((threadIdx.x & 31) == 0) red[threadIdx.x >> 5] = m;
    __syncthreads();
    if (threadIdx.x == 0) {
        float r = red[0];
        #pragma unroll
        for (int w = 1; w < 8; w++) r = fmaxf(r, red[w]);
        atomicMax(outp, __float_as_uint(r));
    }
}

// ---------------- quantize x -> 2-limb int8 ----------------
__global__ __launch_bounds__(256) void xq_kernel(const float* __restrict__ x) {
    size_t i = ((size_t)blockIdx.x * 256 + threadIdx.x) * 4;  // element index, k%4==0
    const float s = 127.f / fmaxf(__uint_as_float(g_xmax_bits), 1e-30f);
    float4 v = *(const float4*)(x + i);
    float vv[4] = {v.x, v.y, v.z, v.w};
    signed char q1[4], q2[4];
    #pragma unroll
    for (int j = 0; j < 4; j++) {
        float aq = vv[j] * s;
        int a1 = __float2int_rn(aq);
        a1 = max(-127, min(127, a1));
        int a2 = __float2int_rn((aq - (float)a1) * 254.f);
        q1[j] = (signed char)a1; q2[j] = (signed char)a2;
    }
    size_t m = i >> 9;
    int k = (int)(i & 511);
    int c = k >> 6, ko = k & 63;
    signed char* dst = g_xq + m * 1024 + c * 128 + ko;
    *(uchar4*)(dst)      = *(uchar4*)q1;
    *(uchar4*)(dst + 64) = *(uchar4*)q2;
}

// ---------------- fused persistent kernel: recurrence + input GEMM -------------
// (Exact R13 structure; ONLY change: tanhf -> tanhf_fast on the serial chain.)
#define R_H    0
#define R_X    16384
#define R_U    32768
#define R_W    65536
#define R_XW   98304
#define R_BIAS 103424
#define R_P    103552
#define REC5_SMEM_BYTES 124032
#define NCTA  128

__global__ __launch_bounds__(256, 1) void lstm_fused_kernel(
    const float* __restrict__ U, const float* __restrict__ W,
    const float* __restrict__ bias, float* __restrict__ out, int write_tail)
{
    extern __shared__ char smem[];
    const uint32_t sb = smem_to_u32(smem);
    const int tid  = threadIdx.x;
    const int wid  = tid >> 5;
    const int lane = tid & 31;
    const int u0   = (blockIdx.x >> 1) * 8;      // unit group
    const int b0   = (blockIdx.x & 1) * 16;      // batch half

    const float s_U = fmaxf(__uint_as_float(g_umax_bits), 1e-30f);
    const float s_X = fmaxf(__uint_as_float(g_xmax_bits), 1e-30f);
    const float s_W = fmaxf(__uint_as_float(g_wmax_bits), 1e-30f);
    const float uinv = 127.f / s_U;
    const float winv = 127.f / s_W;
    const float sc1  = s_U / 16129.f;            // h@U combine scales
    const float sc2  = sc1 / 254.f;
    const float sx1  = s_X * s_W / 16129.f;      // x@W combine scales
    const float sx2  = sx1 / 254.f;

    // ---- quantize U and W slices -> smem int8 2-limb, chunked+swizzled ----
    for (int i = tid; i < 32 * HID; i += 256) {
        int k = i >> 5, n = i & 31;
        int gcol = u0 + (n & 7) + 512 * (n >> 3);
        int c = k >> 6, ko = k & 63;
        uint32_t sw1 = SMEM_SWIZZLE_128B((uint32_t)(n * 128 + ko));
        uint32_t sw2 = SMEM_SWIZZLE_128B((uint32_t)(n * 128 + 64 + ko));
        {
            float v = U[(size_t)k * G4 + gcol];
            float aq = v * uinv;
            int p1 = __float2int_rn(aq);
            p1 = max(-127, min(127, p1));
            int p2 = __float2int_rn((aq - (float)p1) * 254.f);
            uint32_t base = (uint32_t)(R_U + c * 4096);
            *(signed char*)(smem + base + sw1) = (signed char)p1;
            *(signed char*)(smem + base + sw2) = (signed char)p2;
        }
        {
            float v = W[(size_t)k * G4 + gcol];
            float aq = v * winv;
            int p1 = __float2int_rn(aq);
            p1 = max(-127, min(127, p1));
            int p2 = __float2int_rn((aq - (float)p1) * 254.f);
            uint32_t base = (uint32_t)(R_W + c * 4096);
            *(signed char*)(smem + base + sw1) = (signed char)p1;
            *(signed char*)(smem + base + sw2) = (signed char)p2;
        }
    }
    if (tid < 32) {
        int gcol = u0 + (tid & 7) + 512 * (tid >> 3);
        ((float*)(smem + R_BIAS))[tid] = bias[gcol];
    }

    // ldmatrix lane address parts
    const uint32_t aRow = (uint32_t)(lane & 15);
    const uint32_t aCol = (uint32_t)(((lane >> 4) & 1) * 16);
    const uint32_t bRow = (uint32_t)(((lane >> 4) & 1) * 8 + (lane & 7));
    const uint32_t bCol = (uint32_t)(((lane >> 3) & 1) * 16);
    const uint32_t aBase = aRow * 128 + aCol;    // one m-tile (16 rows)
    const uint32_t bBase = bRow * 128 + bCol;    // n-tiles 0-1; +2048 for 2-3

    // activation mapping: thread (tid<128) owns (b = b0 + (tid>>3), u = tid&7)
    const int rb = tid >> 3;
    const int ua = tid & 7;
    float c_state = 0.f;

    float* p_sm = (float*)(smem + R_P);
    const float* bias_sm = (const float*)(smem + R_BIAS);

    // x chunk load for step t: warp w loads chunk w (always commits a group)
    auto issue_x_chunk = [&](int t, int valid) {
        if (valid) {
            const signed char* xq = g_xq + (size_t)t * 32 * 1024;
            #pragma unroll
            for (int j = 0; j < 4; j++) {
                int idx = lane + 32 * j;
                int b = idx >> 3, seg = idx & 7;
                uint32_t sw = SMEM_SWIZZLE_128B((uint32_t)(b * 128 + seg * 16));
                cp_async16(sb + R_X + wid * 2048 + sw,
                           xq + (b0 + b) * 1024 + wid * 128 + seg * 16);
            }
        }
        cp_async_commit();
    };
    // h chunk load: warp w loads chunk w
    auto issue_h_chunk = [&](int R) {
        const signed char* hq = g_hq[R];
        #pragma unroll
        for (int j = 0; j < 4; j++) {
            int idx = lane + 32 * j;
            int b = idx >> 3, seg = idx & 7;
            uint32_t sw = SMEM_SWIZZLE_128B((uint32_t)(b * 128 + seg * 16));
            cp_async16(sb + R_H + wid * 2048 + sw,
                       hq + (b0 + b) * 1024 + wid * 128 + seg * 16);
        }
        cp_async_commit();
    };

    // xw compute for step t into slot t&1: A = x buffer chunk w, B = W chunk w
    auto compute_xw = [&](int t) {
        int X1[4][4], X2[4][4];
        #pragma unroll
        for (int nt = 0; nt < 4; nt++)
            #pragma unroll
            for (int q = 0; q < 4; q++) { X1[nt][q] = 0; X2[nt][q] = 0; }
        const uint32_t xbse = sb + R_X + wid * 2048;
        const uint32_t wbse = sb + R_W + wid * 4096;
        #pragma unroll
        for (int kt = 0; kt < 2; kt++) {
            uint32_t aq1[4], aq2[4], bp1a[4], bp2a[4], bp1b[4], bp2b[4];
            ldmatrix_x4(aq1, xbse + SMEM_SWIZZLE_128B(aBase + kt * 32));
            ldmatrix_x4(aq2, xbse + SMEM_SWIZZLE_128B(aBase + 64 + kt * 32));
            ldmatrix_x4(bp1a, wbse + SMEM_SWIZZLE_128B(bBase + kt * 32));
            ldmatrix_x4(bp2a, wbse + SMEM_SWIZZLE_128B(bBase + 64 + kt * 32));
            ldmatrix_x4(bp1b, wbse + 2048 + SMEM_SWIZZLE_128B(bBase + kt * 32));
            ldmatrix_x4(bp2b, wbse + 2048 + SMEM_SWIZZLE_128B(bBase + 64 + kt * 32));
            #pragma unroll
            for (int nt = 0; nt < 4; nt++) {
                uint32_t* b1 = (nt < 2) ? &bp1a[(nt & 1) * 2] : &bp1b[(nt & 1) * 2];
                uint32_t* b2 = (nt < 2) ? &bp2a[(nt & 1) * 2] : &bp2b[(nt & 1) * 2];
                mma_s8(X1[nt], aq1, b1);
                mma_s8(X2[nt], aq1, b2);
                mma_s8(X2[nt], aq2, b1);
            }
        }
        {
            const int m  = lane >> 2;
            const int nn = 2 * (lane & 3);
            #pragma unroll
            for (int nt = 0; nt < 4; nt++) {
                int col = nt * 8 + nn;
                float e0 = (float)X1[nt][0] * sx1 + (float)X2[nt][0] * sx2;
                float e1 = (float)X1[nt][1] * sx1 + (float)X2[nt][1] * sx2;
                float e2 = (float)X1[nt][2] * sx1 + (float)X2[nt][2] * sx2;
                float e3 = (float)X1[nt][3] * sx1 + (float)X2[nt][3] * sx2;
                *(float2*)&p_sm[(wid * 16 + m) * 40 + col]     = make_float2(e0, e1);
                *(float2*)&p_sm[(wid * 16 + m + 8) * 40 + col] = make_float2(e2, e3);
            }
        }
        __syncthreads();   // xw partials visible
        // fold + bias -> xw_sm slot t&1 (conflict-free reads: n = lane)
        if (tid < 128) {
            int n = tid & 31;
            int bq = (tid >> 5) * 4;
            float* dst = (float*)(smem + R_XW + (uint32_t)((t & 1) * 2560));
            #pragma unroll
            for (int bi = 0; bi < 4; bi++) {
                int b = bq + bi;
                float v = bias_sm[n];
                #pragma unroll
                for (int w = 0; w < 8; w++)
                    v += p_sm[(w * 16 + b) * 40 + n];
                dst[n * 20 + b] = v;
            }
        }
    };

    __syncthreads();            // U/W slices + bias ready

    // ---- prologue: xw(0) into slot 0 ----
    issue_x_chunk(0, 1);
    cp_async_wait<0>();
    compute_xw(0);
    __syncthreads();            // xw(0) ready (and p_sm free)

    for (int t = 0; t < T_STEPS; t++) {
        const int R = t & 1;

        issue_h_chunk(R);                     // group: h(t) chunk w
        issue_x_chunk(t + 1, t + 1 < T_STEPS);// group: x(t+1) (maybe empty)
        cp_async_wait<1>();                   // h ready (x pending)

        // ---- h @ U ----
        int C1[4][4], C2[4][4];
        #pragma unroll
        for (int nt = 0; nt < 4; nt++)
            #pragma unroll
            for (int q = 0; q < 4; q++) { C1[nt][q] = 0; C2[nt][q] = 0; }

        const uint32_t hbse = sb + R_H + wid * 2048;
        const uint32_t ubse = sb + R_U + wid * 4096;
        #pragma unroll
        for (int kt = 0; kt < 2; kt++) {
            uint32_t aq1[4], aq2[4], bp1a[4], bp2a[4], bp1b[4], bp2b[4];
            ldmatrix_x4(aq1, hbse + SMEM_SWIZZLE_128B(aBase + kt * 32));
            ldmatrix_x4(aq2, hbse + SMEM_SWIZZLE_128B(aBase + 64 + kt * 32));
            ldmatrix_x4(bp1a, ubse + SMEM_SWIZZLE_128B(bBase + kt * 32));
            ldmatrix_x4(bp2a, ubse + SMEM_SWIZZLE_128B(bBase + 64 + kt * 32));
            ldmatrix_x4(bp1b, ubse + 2048 + SMEM_SWIZZLE_128B(bBase + kt * 32));
            ldmatrix_x4(bp2b, ubse + 2048 + SMEM_SWIZZLE_128B(bBase + 64 + kt * 32));
            #pragma unroll
            for (int nt = 0; nt < 4; nt++) {
                uint32_t* b1 = (nt < 2) ? &bp1a[(nt & 1) * 2] : &bp1b[(nt & 1) * 2];
                uint32_t* b2 = (nt < 2) ? &bp2a[(nt & 1) * 2] : &bp2b[(nt & 1) * 2];
                mma_s8(C1[nt], aq1, b1);
                mma_s8(C2[nt], aq1, b2);
                mma_s8(C2[nt], aq2, b1);
            }
        }
        {
            const int m  = lane >> 2;
            const int nn = 2 * (lane & 3);
            #pragma unroll
            for (int nt = 0; nt < 4; nt++) {
                int col = nt * 8 + nn;
                float e0 = (float)C1[nt][0] * sc1 + (float)C2[nt][0] * sc2;
                float e1 = (float)C1[nt][1] * sc1 + (float)C2[nt][1] * sc2;
                float e2 = (float)C1[nt][2] * sc1 + (float)C2[nt][2] * sc2;
                float e3 = (float)C1[nt][3] * sc1 + (float)C2[nt][3] * sc2;
                *(float2*)&p_sm[(wid * 16 + m) * 40 + col]     = make_float2(e0, e1);
                *(float2*)&p_sm[(wid * 16 + m + 8) * 40 + col] = make_float2(e2, e3);
            }
        }
        __syncthreads();   // h partials + xw(t) visible

        // ---- reduce + activations (tid < 128): thread owns (rb, ua) ----
        if (tid < 128) {
            const float* xw_sm = (const float*)(smem + R_XW + (uint32_t)((t & 1) * 2560));
            float s[4];
            #pragma unroll
            for (int g = 0; g < 4; g++) {
                int n = g * 8 + ua;
                float v = xw_sm[n * 20 + rb];
                #pragma unroll
                for (int w = 0; w < 8; w++)
                    v += p_sm[(w * 16 + rb) * 40 + n];
                s[g] = v;
            }
            float ig = sigmoidf_(s[0]);
            float fg = sigmoidf_(s[1]);
            float gg = tanhf_fast(s[2]);
            float og = sigmoidf_(s[3]);
            float cnew = fg * c_state + ig * gg;
            float hnew = og * tanhf_fast(cnew);
            c_state = cnew;

            const int b = b0 + rb;
            out[((size_t)t * BATCH + b) * HID + u0 + ua] = hnew;

            float aq = hnew * 127.f;
            int q1 = __float2int_rn(aq);
            q1 = max(-127, min(127, q1));
            int q2 = __float2int_rn((aq - (float)q1) * 254.f);
            int uu = u0 + ua;
            int cc2 = uu >> 6, ko = uu & 63;
            signed char* dst = g_hq[R ^ 1] + b * 1024 + cc2 * 128 + ko;
            dst[0]  = (signed char)q1;
            dst[64] = (signed char)q2;

            if (write_tail && t == T_STEPS - 1) {
                out[(size_t)T_STEPS * BATCH * HID + (size_t)b * HID + u0 + ua] = hnew;
                out[(size_t)T_STEPS * BATCH * HID + BATCH * HID
                    + (size_t)b * HID + u0 + ua] = cnew;
            }
        }
        __syncthreads();   // h stores + p_sm/xw reads complete

        if (t + 1 < T_STEPS) {
            // release EARLY: consumers can start while we compute xw(t+1)
            if (tid == 0) {
                asm volatile("red.release.gpu.add.u32 [%0], %1;"
                             :: "l"(&g_bar), "r"(1u) : "memory");
            }
            // ---- x(t+1) @ W in the barrier bubble ----
            cp_async_wait<0>();   // x(t+1) ready
            compute_xw(t + 1);
            // ---- poll barrier ----
            if (tid == 0) {
                unsigned int target = (unsigned int)NCTA * (unsigned int)(t + 1);
                unsigned int v;
                do {
                    asm volatile("ld.acquire.gpu.u32 %0, [%1];"
                                 : "=r"(v) : "l"(&g_bar) : "memory");
                } while (v < target);
            }
            __syncthreads();      // orders fold reads before next-step p_sm writes
        }
    }
}

// ---------------- launch ----------------
extern "C" void kernel_launch(void* const* d_in, const int* in_sizes, int n_in,
                              void* d_out, int out_size)
{
    const float* x    = (const float*)d_in[0]; // (T,B,I)
    const float* W    = (const float*)d_in[1]; // (I,4H)
    const float* U    = (const float*)d_in[2]; // (H,4H)
    const float* bias = (const float*)d_in[3]; // (4H,)
    float* out = (float*)d_out;

    const long long need_tail = (long long)T_STEPS * BATCH * HID + 2LL * BATCH * HID;
    int write_tail = ((long long)out_size >= need_tail) ? 1 : 0;

    static int configured = 0;
    if (!configured) {
        cudaFuncSetAttribute(lstm_fused_kernel,
                             cudaFuncAttributeMaxDynamicSharedMemorySize,
                             REC5_SMEM_BYTES);
        configured = 1;
    }

    unsigned int* d_umax;
    unsigned int* d_xmax;
    unsigned int* d_wmax;
    cudaGetSymbolAddress((void**)&d_umax, g_umax_bits);
    cudaGetSymbolAddress((void**)&d_xmax, g_xmax_bits);
    cudaGetSymbolAddress((void**)&d_wmax, g_wmax_bits);

    lstm_init_kernel<<<64, 256>>>();
    absmax4_kernel<<<512, 256>>>((const float4*)U, HID * G4 / 4, d_umax);
    absmax4_kernel<<<512, 256>>>((const float4*)W, INP * G4 / 4, d_wmax);
    absmax4_kernel<<<1024, 256>>>((const float4*)x, MTOT * INP / 4, d_xmax);
    xq_kernel<<<(MTOT * INP) / 4 / 256, 256>>>(x);
    lstm_fused_kernel<<<NCTA, 256, REC5_SMEM_BYTES>>>(U, W, bias, out, write_tail);
}

// round 17
// speedup vs baseline: 1.0838x; 1.0305x over previous
#include <cuda_runtime.h>
#include <cuda_bf16.h>
#include <math.h>
#include <stdint.h>

#define T_STEPS 1024
#define BATCH   32
#define INP     512
#define HID     512
#define G4      2048   // 4*HID
#define MTOT    (T_STEPS * BATCH)   // 32768

// ---------------- scratch ----------------
__device__ signed char g_xq[(size_t)MTOT * 1024];    // x 2-limb int8 [m][c*128+limb*64+ko]
__device__ signed char g_hq[2][32 * 1024];           // h 2-limb int8 ping-pong
__device__ unsigned int g_bar;                       // grid barrier counter
__device__ unsigned int g_umax_bits;                 // max|U|
__device__ unsigned int g_xmax_bits;                 // max|x|
__device__ unsigned int g_wmax_bits;                 // max|W|

// ================= helpers =================
__device__ __forceinline__ uint32_t smem_to_u32(const void* p) {
    uint32_t a;
    asm("{ .reg .u64 t; cvta.to.shared.u64 t, %1; cvt.u32.u64 %0, t; }"
        : "=r"(a) : "l"(p));
    return a;
}
#define SMEM_SWIZZLE_128B(off) ((off) ^ (((off) >> 3) & 0x70))

__device__ __forceinline__ void cp_async16(uint32_t smem_addr, const void* gptr) {
    asm volatile("cp.async.cg.shared.global [%0], [%1], 16;"
                 :: "r"(smem_addr), "l"(gptr) : "memory");
}
__device__ __forceinline__ void cp_async_commit() {
    asm volatile("cp.async.commit_group;" ::: "memory");
}
template <int N>
__device__ __forceinline__ void cp_async_wait() {
    asm volatile("cp.async.wait_group %0;" :: "n"(N) : "memory");
}

__device__ __forceinline__ void ldmatrix_x4(uint32_t* r, uint32_t addr) {
    asm volatile("ldmatrix.sync.aligned.m8n8.x4.shared.b16 {%0,%1,%2,%3}, [%4];"
                 : "=r"(r[0]), "=r"(r[1]), "=r"(r[2]), "=r"(r[3]) : "r"(addr));
}
__device__ __forceinline__ void mma_s8(int* c, const uint32_t* a, const uint32_t* b) {
    asm volatile(
        "mma.sync.aligned.m16n8k32.row.col.s32.s8.s8.s32 "
        "{%0,%1,%2,%3}, {%4,%5,%6,%7}, {%8,%9}, {%0,%1,%2,%3};"
        : "+r"(c[0]), "+r"(c[1]), "+r"(c[2]), "+r"(c[3])
        : "r"(a[0]), "r"(a[1]), "r"(a[2]), "r"(a[3]), "r"(b[0]), "r"(b[1]));
}
__device__ __forceinline__ float sigmoidf_(float v) {
    return 1.f / (1.f + __expf(-v));
}

// ---------------- init ----------------
__global__ void lstm_init_kernel() {
    int idx = blockIdx.x * blockDim.x + threadIdx.x;
    int n = 2 * 32 * 1024 / 4;
    for (int i = idx; i < n; i += gridDim.x * blockDim.x)
        ((int*)g_hq)[i] = 0;
    if (idx == 0) { g_bar = 0u; g_umax_bits = 0u; g_xmax_bits = 0u; g_wmax_bits = 0u; }
}

// ---------------- merged max|v| reduction over U, W, x -------------------------
// blocks [0,512): U ; [512,1024): W ; [1024,2048): x
__global__ __launch_bounds__(256) void absmax3_kernel(
    const float4* __restrict__ pU, int nU,
    const float4* __restrict__ pW, int nW,
    const float4* __restrict__ pX, int nX,
    unsigned int* outU, unsigned int* outW, unsigned int* outX)
{
    const float4* p;
    int n, nb, bid;
    unsigned int* outp;
    if (blockIdx.x < 512)       { p = pU; n = nU; nb = 512;  bid = blockIdx.x;        outp = outU; }
    else if (blockIdx.x < 1024) { p = pW; n = nW; nb = 512;  bid = blockIdx.x - 512;  outp = outW; }
    else                        { p = pX; n = nX; nb = 1024; bid = blockIdx.x - 1024; outp = outX; }

    float m0 = 0.f, m1 = 0.f, m2 = 0.f, m3 = 0.f;
    const int stride = nb * 256;
    for (int i = bid * 256 + threadIdx.x; i < n; i += stride) {
        float4 v = p[i];
        m0 = fmaxf(m0, fabsf(v.x));
        m1 = fmaxf(m1, fabsf(v.y));
        m2 = fmaxf(m2, fabsf(v.z));
        m3 = fmaxf(m3, fabsf(v.w));
    }
    float m = fmaxf(fmaxf(m0, m1), fmaxf(m2, m3));
    #pragma unroll
    for (int s = 16; s > 0; s >>= 1)
        m = fmaxf(m, __shfl_xor_sync(0xFFFFFFFFu, m, s));
    __shared__ float red[8];
    if ((threadIdx.x & 31) == 0) red[threadIdx.x >> 5] = m;
    __syncthreads();
    if (threadIdx.x == 0) {
        float r = red[0];
        #pragma unroll
        for (int w = 1; w < 8; w++) r = fmaxf(r, red[w]);
        atomicMax(outp, __float_as_uint(r));
    }
}

// ---------------- quantize x -> 2-limb int8 ----------------
__global__ __launch_bounds__(256) void xq_kernel(const float* __restrict__ x) {
    size_t i = ((size_t)blockIdx.x * 256 + threadIdx.x) * 4;  // element index, k%4==0
    const float s = 127.f / fmaxf(__uint_as_float(g_xmax_bits), 1e-30f);
    float4 v = *(const float4*)(x + i);
    float vv[4] = {v.x, v.y, v.z, v.w};
    signed char q1[4], q2[4];
    #pragma unroll
    for (int j = 0; j < 4; j++) {
        float aq = vv[j] * s;
        int a1 = __float2int_rn(aq);
        a1 = max(-127, min(127, a1));
        int a2 = __float2int_rn((aq - (float)a1) * 254.f);
        q1[j] = (signed char)a1; q2[j] = (signed char)a2;
    }
    size_t m = i >> 9;
    int k = (int)(i & 511);
    int c = k >> 6, ko = k & 63;
    signed char* dst = g_xq + m * 1024 + c * 128 + ko;
    *(uchar4*)(dst)      = *(uchar4*)q1;
    *(uchar4*)(dst + 64) = *(uchar4*)q2;
}

// ---------------- fused persistent kernel: recurrence + input GEMM -------------
// (EXACT R13 structure -- certified best at 2578 us. Do not perturb.)
#define R_H    0
#define R_X    16384
#define R_U    32768
#define R_W    65536
#define R_XW   98304
#define R_BIAS 103424
#define R_P    103552
#define REC5_SMEM_BYTES 124032
#define NCTA  128

__global__ __launch_bounds__(256, 1) void lstm_fused_kernel(
    const float* __restrict__ U, const float* __restrict__ W,
    const float* __restrict__ bias, float* __restrict__ out, int write_tail)
{
    extern __shared__ char smem[];
    const uint32_t sb = smem_to_u32(smem);
    const int tid  = threadIdx.x;
    const int wid  = tid >> 5;
    const int lane = tid & 31;
    const int u0   = (blockIdx.x >> 1) * 8;      // unit group
    const int b0   = (blockIdx.x & 1) * 16;      // batch half

    const float s_U = fmaxf(__uint_as_float(g_umax_bits), 1e-30f);
    const float s_X = fmaxf(__uint_as_float(g_xmax_bits), 1e-30f);
    const float s_W = fmaxf(__uint_as_float(g_wmax_bits), 1e-30f);
    const float uinv = 127.f / s_U;
    const float winv = 127.f / s_W;
    const float sc1  = s_U / 16129.f;            // h@U combine scales
    const float sc2  = sc1 / 254.f;
    const float sx1  = s_X * s_W / 16129.f;      // x@W combine scales
    const float sx2  = sx1 / 254.f;

    // ---- quantize U and W slices -> smem int8 2-limb, chunked+swizzled ----
    for (int i = tid; i < 32 * HID; i += 256) {
        int k = i >> 5, n = i & 31;
        int gcol = u0 + (n & 7) + 512 * (n >> 3);
        int c = k >> 6, ko = k & 63;
        uint32_t sw1 = SMEM_SWIZZLE_128B((uint32_t)(n * 128 + ko));
        uint32_t sw2 = SMEM_SWIZZLE_128B((uint32_t)(n * 128 + 64 + ko));
        {
            float v = U[(size_t)k * G4 + gcol];
            float aq = v * uinv;
            int p1 = __float2int_rn(aq);
            p1 = max(-127, min(127, p1));
            int p2 = __float2int_rn((aq - (float)p1) * 254.f);
            uint32_t base = (uint32_t)(R_U + c * 4096);
            *(signed char*)(smem + base + sw1) = (signed char)p1;
            *(signed char*)(smem + base + sw2) = (signed char)p2;
        }
        {
            float v = W[(size_t)k * G4 + gcol];
            float aq = v * winv;
            int p1 = __float2int_rn(aq);
            p1 = max(-127, min(127, p1));
            int p2 = __float2int_rn((aq - (float)p1) * 254.f);
            uint32_t base = (uint32_t)(R_W + c * 4096);
            *(signed char*)(smem + base + sw1) = (signed char)p1;
            *(signed char*)(smem + base + sw2) = (signed char)p2;
        }
    }
    if (tid < 32) {
        int gcol = u0 + (tid & 7) + 512 * (tid >> 3);
        ((float*)(smem + R_BIAS))[tid] = bias[gcol];
    }

    // ldmatrix lane address parts
    const uint32_t aRow = (uint32_t)(lane & 15);
    const uint32_t aCol = (uint32_t)(((lane >> 4) & 1) * 16);
    const uint32_t bRow = (uint32_t)(((lane >> 4) & 1) * 8 + (lane & 7));
    const uint32_t bCol = (uint32_t)(((lane >> 3) & 1) * 16);
    const uint32_t aBase = aRow * 128 + aCol;    // one m-tile (16 rows)
    const uint32_t bBase = bRow * 128 + bCol;    // n-tiles 0-1; +2048 for 2-3

    // activation mapping: thread (tid<128) owns (b = b0 + (tid>>3), u = tid&7)
    const int rb = tid >> 3;
    const int ua = tid & 7;
    float c_state = 0.f;

    float* p_sm = (float*)(smem + R_P);
    const float* bias_sm = (const float*)(smem + R_BIAS);

    // x chunk load for step t: warp w loads chunk w (always commits a group)
    auto issue_x_chunk = [&](int t, int valid) {
        if (valid) {
            const signed char* xq = g_xq + (size_t)t * 32 * 1024;
            #pragma unroll
            for (int j = 0; j < 4; j++) {
                int idx = lane + 32 * j;
                int b = idx >> 3, seg = idx & 7;
                uint32_t sw = SMEM_SWIZZLE_128B((uint32_t)(b * 128 + seg * 16));
                cp_async16(sb + R_X + wid * 2048 + sw,
                           xq + (b0 + b) * 1024 + wid * 128 + seg * 16);
            }
        }
        cp_async_commit();
    };
    // h chunk load: warp w loads chunk w
    auto issue_h_chunk = [&](int R) {
        const signed char* hq = g_hq[R];
        #pragma unroll
        for (int j = 0; j < 4; j++) {
            int idx = lane + 32 * j;
            int b = idx >> 3, seg = idx & 7;
            uint32_t sw = SMEM_SWIZZLE_128B((uint32_t)(b * 128 + seg * 16));
            cp_async16(sb + R_H + wid * 2048 + sw,
                       hq + (b0 + b) * 1024 + wid * 128 + seg * 16);
        }
        cp_async_commit();
    };

    // xw compute for step t into slot t&1: A = x buffer chunk w, B = W chunk w
    auto compute_xw = [&](int t) {
        int X1[4][4], X2[4][4];
        #pragma unroll
        for (int nt = 0; nt < 4; nt++)
            #pragma unroll
            for (int q = 0; q < 4; q++) { X1[nt][q] = 0; X2[nt][q] = 0; }
        const uint32_t xbse = sb + R_X + wid * 2048;
        const uint32_t wbse = sb + R_W + wid * 4096;
        #pragma unroll
        for (int kt = 0; kt < 2; kt++) {
            uint32_t aq1[4], aq2[4], bp1a[4], bp2a[4], bp1b[4], bp2b[4];
            ldmatrix_x4(aq1, xbse + SMEM_SWIZZLE_128B(aBase + kt * 32));
            ldmatrix_x4(aq2, xbse + SMEM_SWIZZLE_128B(aBase + 64 + kt * 32));
            ldmatrix_x4(bp1a, wbse + SMEM_SWIZZLE_128B(bBase + kt * 32));
            ldmatrix_x4(bp2a, wbse + SMEM_SWIZZLE_128B(bBase + 64 + kt * 32));
            ldmatrix_x4(bp1b, wbse + 2048 + SMEM_SWIZZLE_128B(bBase + kt * 32));
            ldmatrix_x4(bp2b, wbse + 2048 + SMEM_SWIZZLE_128B(bBase + 64 + kt * 32));
            #pragma unroll
            for (int nt = 0; nt < 4; nt++) {
                uint32_t* b1 = (nt < 2) ? &bp1a[(nt & 1) * 2] : &bp1b[(nt & 1) * 2];
                uint32_t* b2 = (nt < 2) ? &bp2a[(nt & 1) * 2] : &bp2b[(nt & 1) * 2];
                mma_s8(X1[nt], aq1, b1);
                mma_s8(X2[nt], aq1, b2);
                mma_s8(X2[nt], aq2, b1);
            }
        }
        {
            const int m  = lane >> 2;
            const int nn = 2 * (lane & 3);
            #pragma unroll
            for (int nt = 0; nt < 4; nt++) {
                int col = nt * 8 + nn;
                float e0 = (float)X1[nt][0] * sx1 + (float)X2[nt][0] * sx2;
                float e1 = (float)X1[nt][1] * sx1 + (float)X2[nt][1] * sx2;
                float e2 = (float)X1[nt][2] * sx1 + (float)X2[nt][2] * sx2;
                float e3 = (float)X1[nt][3] * sx1 + (float)X2[nt][3] * sx2;
                *(float2*)&p_sm[(wid * 16 + m) * 40 + col]     = make_float2(e0, e1);
                *(float2*)&p_sm[(wid * 16 + m + 8) * 40 + col] = make_float2(e2, e3);
            }
        }
        __syncthreads();   // xw partials visible
        // fold + bias -> xw_sm slot t&1 (conflict-free reads: n = lane)
        if (tid < 128) {
            int n = tid & 31;
            int bq = (tid >> 5) * 4;
            float* dst = (float*)(smem + R_XW + (uint32_t)((t & 1) * 2560));
            #pragma unroll
            for (int bi = 0; bi < 4; bi++) {
                int b = bq + bi;
                float v = bias_sm[n];
                #pragma unroll
                for (int w = 0; w < 8; w++)
                    v += p_sm[(w * 16 + b) * 40 + n];
                dst[n * 20 + b] = v;
            }
        }
    };

    __syncthreads();            // U/W slices + bias ready

    // ---- prologue: xw(0) into slot 0 ----
    issue_x_chunk(0, 1);
    cp_async_wait<0>();
    compute_xw(0);
    __syncthreads();            // xw(0) ready (and p_sm free)

    for (int t = 0; t < T_STEPS; t++) {
        const int R = t & 1;

        issue_h_chunk(R);                     // group: h(t) chunk w
        issue_x_chunk(t + 1, t + 1 < T_STEPS);// group: x(t+1) (maybe empty)
        cp_async_wait<1>();                   // h ready (x pending)

        // ---- h @ U ----
        int C1[4][4], C2[4][4];
        #pragma unroll
        for (int nt = 0; nt < 4; nt++)
            #pragma unroll
            for (int q = 0; q < 4; q++) { C1[nt][q] = 0; C2[nt][q] = 0; }

        const uint32_t hbse = sb + R_H + wid * 2048;
        const uint32_t ubse = sb + R_U + wid * 4096;
        #pragma unroll
        for (int kt = 0; kt < 2; kt++) {
            uint32_t aq1[4], aq2[4], bp1a[4], bp2a[4], bp1b[4], bp2b[4];
            ldmatrix_x4(aq1, hbse + SMEM_SWIZZLE_128B(aBase + kt * 32));
            ldmatrix_x4(aq2, hbse + SMEM_SWIZZLE_128B(aBase + 64 + kt * 32));
            ldmatrix_x4(bp1a, ubse + SMEM_SWIZZLE_128B(bBase + kt * 32));
            ldmatrix_x4(bp2a, ubse + SMEM_SWIZZLE_128B(bBase + 64 + kt * 32));
            ldmatrix_x4(bp1b, ubse + 2048 + SMEM_SWIZZLE_128B(bBase + kt * 32));
            ldmatrix_x4(bp2b, ubse + 2048 + SMEM_SWIZZLE_128B(bBase + 64 + kt * 32));
            #pragma unroll
            for (int nt = 0; nt < 4; nt++) {
                uint32_t* b1 = (nt < 2) ? &bp1a[(nt & 1) * 2] : &bp1b[(nt & 1) * 2];
                uint32_t* b2 = (nt < 2) ? &bp2a[(nt & 1) * 2] : &bp2b[(nt & 1) * 2];
                mma_s8(C1[nt], aq1, b1);
                mma_s8(C2[nt], aq1, b2);
                mma_s8(C2[nt], aq2, b1);
            }
        }
        {
            const int m  = lane >> 2;
            const int nn = 2 * (lane & 3);
            #pragma unroll
            for (int nt = 0; nt < 4; nt++) {
                int col = nt * 8 + nn;
                float e0 = (float)C1[nt][0] * sc1 + (float)C2[nt][0] * sc2;
                float e1 = (float)C1[nt][1] * sc1 + (float)C2[nt][1] * sc2;
                float e2 = (float)C1[nt][2] * sc1 + (float)C2[nt][2] * sc2;
                float e3 = (float)C1[nt][3] * sc1 + (float)C2[nt][3] * sc2;
                *(float2*)&p_sm[(wid * 16 + m) * 40 + col]     = make_float2(e0, e1);
                *(float2*)&p_sm[(wid * 16 + m + 8) * 40 + col] = make_float2(e2, e3);
            }
        }
        __syncthreads();   // h partials + xw(t) visible

        // ---- reduce + activations (tid < 128): thread owns (rb, ua) ----
        if (tid < 128) {
            const float* xw_sm = (const float*)(smem + R_XW + (uint32_t)((t & 1) * 2560));
            float s[4];
            #pragma unroll
            for (int g = 0; g < 4; g++) {
                int n = g * 8 + ua;
                float v = xw_sm[n * 20 + rb];
                #pragma unroll
                for (int w = 0; w < 8; w++)
                    v += p_sm[(w * 16 + rb) * 40 + n];
                s[g] = v;
            }
            float ig = sigmoidf_(s[0]);
            float fg = sigmoidf_(s[1]);
            float gg = tanhf(s[2]);
            float og = sigmoidf_(s[3]);
            float cnew = fg * c_state + ig * gg;
            float hnew = og * tanhf(cnew);
            c_state = cnew;

            const int b = b0 + rb;
            out[((size_t)t * BATCH + b) * HID + u0 + ua] = hnew;

            float aq = hnew * 127.f;
            int q1 = __float2int_rn(aq);
            q1 = max(-127, min(127, q1));
            int q2 = __float2int_rn((aq - (float)q1) * 254.f);
            int uu = u0 + ua;
            int cc2 = uu >> 6, ko = uu & 63;
            signed char* dst = g_hq[R ^ 1] + b * 1024 + cc2 * 128 + ko;
            dst[0]  = (signed char)q1;
            dst[64] = (signed char)q2;

            if (write_tail && t == T_STEPS - 1) {
                out[(size_t)T_STEPS * BATCH * HID + (size_t)b * HID + u0 + ua] = hnew;
                out[(size_t)T_STEPS * BATCH * HID + BATCH * HID
                    + (size_t)b * HID + u0 + ua] = cnew;
            }
        }
        __syncthreads();   // h stores + p_sm/xw reads complete

        if (t + 1 < T_STEPS) {
            // release EARLY: consumers can start while we compute xw(t+1)
            if (tid == 0) {
                asm volatile("red.release.gpu.add.u32 [%0], %1;"
                             :: "l"(&g_bar), "r"(1u) : "memory");
            }
            // ---- x(t+1) @ W in the barrier bubble ----
            cp_async_wait<0>();   // x(t+1) ready
            compute_xw(t + 1);
            // ---- poll barrier ----
            if (tid == 0) {
                unsigned int target = (unsigned int)NCTA * (unsigned int)(t + 1);
                unsigned int v;
                do {
                    asm volatile("ld.acquire.gpu.u32 %0, [%1];"
                                 : "=r"(v) : "l"(&g_bar) : "memory");
                } while (v < target);
            }
            __syncthreads();      // orders fold reads before next-step p_sm writes
        }
    }
}

// ---------------- launch ----------------
extern "C" void kernel_launch(void* const* d_in, const int* in_sizes, int n_in,
                              void* d_out, int out_size)
{
    const float* x    = (const float*)d_in[0]; // (T,B,I)
    const float* W    = (const float*)d_in[1]; // (I,4H)
    const float* U    = (const float*)d_in[2]; // (H,4H)
    const float* bias = (const float*)d_in[3]; // (4H,)
    float* out = (float*)d_out;

    const long long need_tail = (long long)T_STEPS * BATCH * HID + 2LL * BATCH * HID;
    int write_tail = ((long long)out_size >= need_tail) ? 1 : 0;

    static int configured = 0;
    if (!configured) {
        cudaFuncSetAttribute(lstm_fused_kernel,
                             cudaFuncAttributeMaxDynamicSharedMemorySize,
                             REC5_SMEM_BYTES);
        configured = 1;
    }

    unsigned int* d_umax;
    unsigned int* d_xmax;
    unsigned int* d_wmax;
    cudaGetSymbolAddress((void**)&d_umax, g_umax_bits);
    cudaGetSymbolAddress((void**)&d_xmax, g_xmax_bits);
    cudaGetSymbolAddress((void**)&d_wmax, g_wmax_bits);

    lstm_init_kernel<<<64, 256>>>();
    absmax3_kernel<<<2048, 256>>>(
        (const float4*)U, HID * G4 / 4,
        (const float4*)W, INP * G4 / 4,
        (const float4*)x, MTOT * INP / 4,
        d_umax, d_wmax, d_xmax);
    xq_kernel<<<(MTOT * INP) / 4 / 256, 256>>>(x);
    lstm_fused_kernel<<<NCTA, 256, REC5_SMEM_BYTES>>>(U, W, bias, out, write_tail);
}